// round 4
// baseline (speedup 1.0000x reference)
#include <cuda_runtime.h>

// Problem constants (fixed by the reference)
#define NB_B   512
#define NB_CIN 5
#define NB_L   1024
#define NB_NCH 64     // 2*COUT
#define NB_A   13
#define NB_NB  5

typedef unsigned long long u64;

// ---------------- scratch (static device globals; no allocation) ----------------
__device__ float g_part[NB_B][128];          // per-b partial sum(64) + sumsq(64)
__device__ float g_ab[2][NB_NCH];            // BN affine: scale a, shift beta
__device__ float g_S[10];                    // column sums of flw halves
__device__ float g_F[NB_B * NB_NCH * 10];    // F[b][ch][j], j = half*5+n

// ---------------- packed f32x2 helpers (Blackwell) ----------------
__device__ __forceinline__ u64 fma2(u64 a, u64 b, u64 c) {
    u64 d; asm("fma.rn.f32x2 %0, %1, %2, %3;" : "=l"(d) : "l"(a), "l"(b), "l"(c)); return d;
}
__device__ __forceinline__ u64 add2(u64 a, u64 b) {
    u64 d; asm("add.rn.f32x2 %0, %1, %2;" : "=l"(d) : "l"(a), "l"(b)); return d;
}
__device__ __forceinline__ u64 pack2(float x, float y) {
    u64 r; asm("mov.b64 %0, {%1, %2};" : "=l"(r) : "f"(x), "f"(y)); return r;
}
__device__ __forceinline__ void unpack2(u64 v, float& x, float& y) {
    asm("mov.b64 {%0, %1}, %2;" : "=f"(x), "=f"(y) : "l"(v));
}

// ---------------- shared layout (floats) ----------------
#define OFF_SRC  0
#define OFF_D    (NB_CIN * NB_L)            // 5120  : d1[5][1024], d2[5][1024]
#define OFF_REDA (OFF_D + 10 * NB_L)        // 15360 : kernel A reduction (512)
#define SMEM_A_FLOATS (OFF_REDA + 512)      // 15872 -> 63488 B
#define OFF_FLW  (OFF_D + 10 * NB_L)        // 15360 : kernel C flw stage (10240)
#define OFF_REDC (OFF_FLW + 10 * NB_L)      // 25600 : kernel C reduction (2560)
#define SMEM_C_FLOATS (OFF_REDC + 64*4*10)  // 28160 -> 112640 B

// Stage one batch row of src into shared and compute both depthwise convs.
// Caller must __syncthreads() afterwards.
__device__ __forceinline__ void stage_src_and_conv(
    const float* __restrict__ src_b,
    const float* __restrict__ dw1, const float* __restrict__ dw2,
    float* sm, int tid)
{
    float4*       sdst = reinterpret_cast<float4*>(sm + OFF_SRC);
    const float4* ssrc = reinterpret_cast<const float4*>(src_b);
    #pragma unroll
    for (int i = 0; i < 5; i++) sdst[tid + i * 256] = ssrc[tid + i * 256]; // 1280 f4
    __syncthreads();

    float w1[25], w2[15];
    #pragma unroll
    for (int i = 0; i < 25; i++) w1[i] = __ldg(dw1 + i);
    #pragma unroll
    for (int i = 0; i < 15; i++) w2[i] = __ldg(dw2 + i);

    #pragma unroll
    for (int it = 0; it < 4; it++) {
        int l = tid + it * 256;
        #pragma unroll
        for (int c = 0; c < 5; c++) {
            const float* sc = sm + OFF_SRC + c * NB_L;
            float xm2 = (l >= 2)        ? sc[l - 2] : 0.f;
            float xm1 = (l >= 1)        ? sc[l - 1] : 0.f;
            float x0  =                   sc[l];
            float xp1 = (l < NB_L - 1)  ? sc[l + 1] : 0.f;
            float xp2 = (l < NB_L - 2)  ? sc[l + 2] : 0.f;
            sm[OFF_D + c * NB_L + l] =
                w1[c*5+0]*xm2 + w1[c*5+1]*xm1 + w1[c*5+2]*x0 + w1[c*5+3]*xp1 + w1[c*5+4]*xp2;
            sm[OFF_D + (5 + c) * NB_L + l] =
                w2[c*3+0]*xm1 + w2[c*3+1]*x0 + w2[c*3+2]*xp1;
        }
    }
}

// ---------------- Kernel A: per-(b) partial BN statistics of y ----------------
__global__ void __launch_bounds__(256) k_stats(
    const float* __restrict__ src,
    const float* __restrict__ dw1, const float* __restrict__ pw1,
    const float* __restrict__ dw2, const float* __restrict__ pw2)
{
    extern __shared__ float sm[];
    int b = blockIdx.x, tid = threadIdx.x;
    stage_src_and_conv(src + (size_t)b * (NB_CIN * NB_L), dw1, dw2, sm, tid);
    __syncthreads();

    int ch = tid & 63, lg = tid >> 6;       // warp lanes share lg -> all LDS are broadcasts
    int br = ch >> 5, o = ch & 31;
    const float* pw = (br ? pw2 : pw1) + o * 5;
    u64 w[5];
    #pragma unroll
    for (int c = 0; c < 5; c++) { float v = __ldg(pw + c); w[c] = pack2(v, v); }

    const float* dbase = sm + OFF_D + br * 5 * NB_L;
    u64 s2 = 0, q2 = 0;
    #pragma unroll 4
    for (int k = 0; k < 64; k++) {
        int l0 = (lg + 4 * k) * 4;          // quad of l values, 16B aligned
        u64 y01 = 0, y23 = 0;
        #pragma unroll
        for (int c = 0; c < 5; c++) {
            ulonglong2 dv = *reinterpret_cast<const ulonglong2*>(dbase + c * NB_L + l0);
            y01 = fma2(w[c], dv.x, y01);
            y23 = fma2(w[c], dv.y, y23);
        }
        s2 = add2(s2, add2(y01, y23));
        q2 = fma2(y01, y01, q2);
        q2 = fma2(y23, y23, q2);
    }
    float sa, sb, qa, qb;
    unpack2(s2, sa, sb); unpack2(q2, qa, qb);
    sm[OFF_REDA + ch * 4 + lg]       = sa + sb;
    sm[OFF_REDA + 256 + ch * 4 + lg] = qa + qb;
    __syncthreads();
    if (tid < 64) {
        const float* r = sm + OFF_REDA + tid * 4;
        g_part[b][tid]      = r[0] + r[1] + r[2] + r[3];
        const float* q = sm + OFF_REDA + 256 + tid * 4;
        g_part[b][64 + tid] = q[0] + q[1] + q[2] + q[3];
    }
}

// ---------------- Kernel B: finalize BN affine + flw column sums ----------------
__global__ void k_finalize(
    const float* __restrict__ g1, const float* __restrict__ be1,
    const float* __restrict__ g2, const float* __restrict__ be2,
    const float* __restrict__ flw)
{
    int t = threadIdx.x;
    if (t < 64) {
        float s = 0.f, q = 0.f;
        for (int b = 0; b < NB_B; b++) { s += g_part[b][t]; q += g_part[b][64 + t]; }
        const float inv_n = 1.f / (float)(NB_B * NB_L);
        float mean = s * inv_n;
        float var  = q * inv_n - mean * mean;
        float gg = (t < 32) ? __ldg(g1 + t)  : __ldg(g2 + t - 32);
        float bb = (t < 32) ? __ldg(be1 + t) : __ldg(be2 + t - 32);
        float a = gg * rsqrtf(var + 1e-5f);
        g_ab[0][t] = a;
        g_ab[1][t] = bb - mean * a;
    } else if (t < 74) {
        int j = t - 64;                      // j = half*5 + n
        int n = j % 5, half = j / 5;
        const float* p = flw + n * 2048 + half * 1024;
        float s = 0.f;
        for (int l = 0; l < 1024; l++) s += p[l];
        g_S[j] = s;
    }
}

// ---------------- Kernel C: fused BN/ReLU/residual + F accumulation ----------------
__global__ void __launch_bounds__(256) k_pass2(
    const float* __restrict__ src,
    const float* __restrict__ dw1, const float* __restrict__ pw1,
    const float* __restrict__ r1w, const float* __restrict__ r1b,
    const float* __restrict__ dw2, const float* __restrict__ pw2,
    const float* __restrict__ r2w, const float* __restrict__ r2b,
    const float* __restrict__ flw)
{
    extern __shared__ float sm[];
    int b = blockIdx.x, tid = threadIdx.x;

    { // stage flw (L2-resident, 40KB) into shared
        float4*       fdst = reinterpret_cast<float4*>(sm + OFF_FLW);
        const float4* fsrc = reinterpret_cast<const float4*>(flw);
        #pragma unroll
        for (int i = 0; i < 10; i++) fdst[tid + i * 256] = fsrc[tid + i * 256]; // 2560 f4
    }
    stage_src_and_conv(src + (size_t)b * (NB_CIN * NB_L), dw1, dw2, sm, tid);
    __syncthreads();

    int ch = tid & 63, lg = tid >> 6;
    int br = ch >> 5, o = ch & 31;
    const float* pw = (br ? pw2 : pw1) + o * 5;
    const float* rw = (br ? r2w : r1w) + o * 5;
    float rbv = br ? __ldg(r2b + o) : __ldg(r1b + o);
    u64 w[5], rwp[5];
    #pragma unroll
    for (int c = 0; c < 5; c++) {
        float v = __ldg(pw + c); w[c]   = pack2(v, v);
        float u = __ldg(rw + c); rwp[c] = pack2(u, u);
    }
    float av = g_ab[0][ch], bv = g_ab[1][ch];
    u64 a2 = pack2(av, av), bb2 = pack2(bv, bv), rb2 = pack2(rbv, rbv);

    const float* dbase = sm + OFF_D + br * 5 * NB_L;
    const float* sbase = sm + OFF_SRC;
    const float* fbase = sm + OFF_FLW;

    u64 F[10];
    #pragma unroll
    for (int j = 0; j < 10; j++) F[j] = 0;

    for (int k = 0; k < 64; k++) {
        int l0 = (lg + 4 * k) * 4;
        u64 y01 = 0, y23 = 0, r01 = rb2, r23 = rb2;
        #pragma unroll
        for (int c = 0; c < 5; c++) {
            ulonglong2 dv = *reinterpret_cast<const ulonglong2*>(dbase + c * NB_L + l0);
            y01 = fma2(w[c], dv.x, y01);
            y23 = fma2(w[c], dv.y, y23);
            ulonglong2 sv = *reinterpret_cast<const ulonglong2*>(sbase + c * NB_L + l0);
            r01 = fma2(rwp[c], sv.x, r01);
            r23 = fma2(rwp[c], sv.y, r23);
        }
        u64 t01 = fma2(a2, y01, bb2);
        u64 t23 = fma2(a2, y23, bb2);
        float t0, t1, t2, t3, ra0, ra1, ra2, ra3;
        unpack2(t01, t0, t1); unpack2(t23, t2, t3);
        unpack2(r01, ra0, ra1); unpack2(r23, ra2, ra3);
        u64 e01 = pack2(fmaxf(t0, 0.f) * ra0, fmaxf(t1, 0.f) * ra1);
        u64 e23 = pack2(fmaxf(t2, 0.f) * ra2, fmaxf(t3, 0.f) * ra3);
        #pragma unroll
        for (int n = 0; n < 5; n++) {
            ulonglong2 f1 = *reinterpret_cast<const ulonglong2*>(fbase + n * 2048 + l0);
            F[n]     = fma2(e01, f1.x, F[n]);
            F[n]     = fma2(e23, f1.y, F[n]);
            ulonglong2 f2 = *reinterpret_cast<const ulonglong2*>(fbase + n * 2048 + 1024 + l0);
            F[5 + n] = fma2(e01, f2.x, F[5 + n]);
            F[5 + n] = fma2(e23, f2.y, F[5 + n]);
        }
    }
    #pragma unroll
    for (int j = 0; j < 10; j++) {
        float x, y; unpack2(F[j], x, y);
        sm[OFF_REDC + (ch * 4 + lg) * 10 + j] = x + y;
    }
    __syncthreads();
    if (tid < 64) {
        #pragma unroll
        for (int j = 0; j < 10; j++) {
            const float* r = sm + OFF_REDC + tid * 40 + j;
            g_F[(b * 64 + tid) * 10 + j] = r[0] + r[10] + r[20] + r[30];
        }
    }
}

// ---------------- Kernel D: G = ll1w . F, then (i,j) gather-add output ----------------
__global__ void __launch_bounds__(256) k_out(
    const float* __restrict__ ll1w, const float* __restrict__ ll1b,
    const float* __restrict__ flb, float* __restrict__ out)
{
    __shared__ float sF[640], sW[832], sG[130], sbb[13], sfb[5], sS[10];
    int b = blockIdx.x, t = threadIdx.x;
    for (int i = t; i < 640; i += 256) sF[i] = g_F[b * 640 + i];
    for (int i = t; i < 832; i += 256) sW[i] = __ldg(ll1w + i);
    if (t < 13) sbb[t] = __ldg(ll1b + t);
    if (t < 5)  sfb[t] = __ldg(flb + t);
    if (t < 10) sS[t]  = g_S[t];
    __syncthreads();
    if (t < 130) {
        int a = t / 10, j = t % 10;
        float acc = sbb[a] * sS[j];
        #pragma unroll 8
        for (int c = 0; c < 64; c++) acc += sW[a * 64 + c] * sF[c * 10 + j];
        sG[t] = acc;          // sG[a*10+j], j<5: half0 (min), j>=5: half1 (max)
    }
    __syncthreads();
    float* ob = out + (size_t)b * (NB_A * NB_A * NB_NB);
    for (int idx = t; idx < NB_A * NB_A * NB_NB; idx += 256) {
        int i  = idx / (NB_A * NB_NB);
        int r  = idx % (NB_A * NB_NB);
        int jj = r / NB_NB, n = r % NB_NB;
        int mn = min(i, jj), mx = max(i, jj);
        ob[idx] = sG[mn * 10 + n] + sG[mx * 10 + 5 + n] + sfb[n];
    }
}

// ---------------- launcher ----------------
extern "C" void kernel_launch(void* const* d_in, const int* in_sizes, int n_in,
                              void* d_out, int out_size)
{
    // dw1 is the unique size-25 tensor; everything after it is in fixed order.
    int i0 = -1;
    for (int i = 0; i < n_in; i++) if (in_sizes[i] == 25) { i0 = i; break; }
    if (i0 < 0) i0 = 3; // fallback: src, mask, max_atoms, dw1, ...

    const float* src  = (const float*)d_in[0];
    const float* dw1  = (const float*)d_in[i0 + 0];
    const float* pw1  = (const float*)d_in[i0 + 1];
    const float* g1   = (const float*)d_in[i0 + 2];
    const float* be1  = (const float*)d_in[i0 + 3];
    const float* r1w  = (const float*)d_in[i0 + 4];
    const float* r1b  = (const float*)d_in[i0 + 5];
    const float* dw2  = (const float*)d_in[i0 + 6];
    const float* pw2  = (const float*)d_in[i0 + 7];
    const float* g2   = (const float*)d_in[i0 + 8];
    const float* be2  = (const float*)d_in[i0 + 9];
    const float* r2w  = (const float*)d_in[i0 + 10];
    const float* r2b  = (const float*)d_in[i0 + 11];
    const float* ll1w = (const float*)d_in[i0 + 12];
    const float* ll1b = (const float*)d_in[i0 + 13];
    const float* flw  = (const float*)d_in[i0 + 14];
    const float* flb  = (const float*)d_in[i0 + 15];
    float* out = (float*)d_out;
    (void)out_size; (void)n_in;

    const int shA = SMEM_A_FLOATS * (int)sizeof(float);   // 63488 B
    const int shC = SMEM_C_FLOATS * (int)sizeof(float);   // 112640 B
    cudaFuncSetAttribute(k_stats, cudaFuncAttributeMaxDynamicSharedMemorySize, shA);
    cudaFuncSetAttribute(k_pass2, cudaFuncAttributeMaxDynamicSharedMemorySize, shC);

    k_stats<<<NB_B, 256, shA>>>(src, dw1, pw1, dw2, pw2);
    k_finalize<<<1, 128>>>(g1, be1, g2, be2, flw);
    k_pass2<<<NB_B, 256, shC>>>(src, dw1, pw1, r1w, r1b, dw2, pw2, r2w, r2b, flw);
    k_out<<<NB_B, 256>>>(ll1w, ll1b, flb, out);
}

// round 5
// speedup vs baseline: 1.8923x; 1.8923x over previous
#include <cuda_runtime.h>

// Problem constants (fixed by the reference)
#define NB_B   512
#define NB_CIN 5
#define NB_L   1024
#define NB_NCH 64     // 2*COUT
#define NB_A   13
#define NB_NB  5

typedef unsigned long long u64;

// ---------------- scratch (static device globals; no allocation) ----------------
__device__ float g_part[NB_B][128];          // per-b partial sum(64) + sumsq(64)
__device__ float g_ab[2][NB_NCH];            // BN affine: scale a, shift beta
__device__ float g_S[10];                    // column sums of flw halves

// ---------------- packed f32x2 helpers (Blackwell) ----------------
__device__ __forceinline__ u64 fma2(u64 a, u64 b, u64 c) {
    u64 d; asm("fma.rn.f32x2 %0, %1, %2, %3;" : "=l"(d) : "l"(a), "l"(b), "l"(c)); return d;
}
__device__ __forceinline__ u64 add2(u64 a, u64 b) {
    u64 d; asm("add.rn.f32x2 %0, %1, %2;" : "=l"(d) : "l"(a), "l"(b)); return d;
}
__device__ __forceinline__ u64 pack2(float x, float y) {
    u64 r; asm("mov.b64 %0, {%1, %2};" : "=l"(r) : "f"(x), "f"(y)); return r;
}
__device__ __forceinline__ void unpack2(u64 v, float& x, float& y) {
    asm("mov.b64 {%0, %1}, %2;" : "=f"(x), "=f"(y) : "l"(v));
}

// ---------------- shared layout (floats) ----------------
#define OFF_SRC  0
#define OFF_D    (NB_CIN * NB_L)            // 5120  : d1[5][1024], d2[5][1024]
#define OFF_REDA (OFF_D + 10 * NB_L)        // 15360 : kernel A reduction (512)
#define SMEM_A_FLOATS (OFF_REDA + 512)      // 15872 -> 63488 B
#define OFF_FLW  (OFF_D + 10 * NB_L)        // 15360 : kernel C flw stage (10240)
#define OFF_REDC (OFF_FLW + 10 * NB_L)      // 25600 : kernel C reduction (2560)
#define SMEM_C_FLOATS (OFF_REDC + 64*4*10)  // 28160 -> 112640 B

// Epilogue aliases into the (dead-after-mainloop) src region of kernel C smem
#define EP_W   (OFF_SRC)          // 832  : ll1w
#define EP_F   (EP_W + 832)       // 640  : reduced F[ch][j]
#define EP_G   (EP_F + 640)       // 130
#define EP_BB  (EP_G + 130)       // 13   : ll1b
#define EP_S   (EP_BB + 13)       // 10   : g_S
#define EP_FB  (EP_S + 10)        // 5    : flb

// Stage one batch row of src into shared and compute both depthwise convs.
// Caller must __syncthreads() afterwards.
__device__ __forceinline__ void stage_src_and_conv(
    const float* __restrict__ src_b,
    const float* __restrict__ dw1, const float* __restrict__ dw2,
    float* sm, int tid)
{
    float4*       sdst = reinterpret_cast<float4*>(sm + OFF_SRC);
    const float4* ssrc = reinterpret_cast<const float4*>(src_b);
    #pragma unroll
    for (int i = 0; i < 5; i++) sdst[tid + i * 256] = ssrc[tid + i * 256]; // 1280 f4
    __syncthreads();

    float w1[25], w2[15];
    #pragma unroll
    for (int i = 0; i < 25; i++) w1[i] = __ldg(dw1 + i);
    #pragma unroll
    for (int i = 0; i < 15; i++) w2[i] = __ldg(dw2 + i);

    #pragma unroll
    for (int it = 0; it < 4; it++) {
        int l = tid + it * 256;
        #pragma unroll
        for (int c = 0; c < 5; c++) {
            const float* sc = sm + OFF_SRC + c * NB_L;
            float xm2 = (l >= 2)        ? sc[l - 2] : 0.f;
            float xm1 = (l >= 1)        ? sc[l - 1] : 0.f;
            float x0  =                   sc[l];
            float xp1 = (l < NB_L - 1)  ? sc[l + 1] : 0.f;
            float xp2 = (l < NB_L - 2)  ? sc[l + 2] : 0.f;
            sm[OFF_D + c * NB_L + l] =
                w1[c*5+0]*xm2 + w1[c*5+1]*xm1 + w1[c*5+2]*x0 + w1[c*5+3]*xp1 + w1[c*5+4]*xp2;
            sm[OFF_D + (5 + c) * NB_L + l] =
                w2[c*3+0]*xm1 + w2[c*3+1]*x0 + w2[c*3+2]*xp1;
        }
    }
}

// ---------------- Kernel A: per-(b) partial BN statistics of y ----------------
__global__ void __launch_bounds__(256) k_stats(
    const float* __restrict__ src,
    const float* __restrict__ dw1, const float* __restrict__ pw1,
    const float* __restrict__ dw2, const float* __restrict__ pw2)
{
    extern __shared__ float sm[];
    int b = blockIdx.x, tid = threadIdx.x;
    stage_src_and_conv(src + (size_t)b * (NB_CIN * NB_L), dw1, dw2, sm, tid);
    __syncthreads();

    int ch = tid & 63, lg = tid >> 6;       // warp lanes share lg -> all LDS are broadcasts
    int br = ch >> 5, o = ch & 31;
    const float* pw = (br ? pw2 : pw1) + o * 5;
    u64 w[5];
    #pragma unroll
    for (int c = 0; c < 5; c++) { float v = __ldg(pw + c); w[c] = pack2(v, v); }

    const float* dbase = sm + OFF_D + br * 5 * NB_L;
    u64 s2 = 0, q2 = 0;
    #pragma unroll 4
    for (int k = 0; k < 64; k++) {
        int l0 = (lg + 4 * k) * 4;          // quad of l values, 16B aligned
        u64 y01 = 0, y23 = 0;
        #pragma unroll
        for (int c = 0; c < 5; c++) {
            ulonglong2 dv = *reinterpret_cast<const ulonglong2*>(dbase + c * NB_L + l0);
            y01 = fma2(w[c], dv.x, y01);
            y23 = fma2(w[c], dv.y, y23);
        }
        s2 = add2(s2, add2(y01, y23));
        q2 = fma2(y01, y01, q2);
        q2 = fma2(y23, y23, q2);
    }
    float sa, sb, qa, qb;
    unpack2(s2, sa, sb); unpack2(q2, qa, qb);
    sm[OFF_REDA + ch * 4 + lg]       = sa + sb;
    sm[OFF_REDA + 256 + ch * 4 + lg] = qa + qb;
    __syncthreads();
    if (tid < 64) {
        const float* r = sm + OFF_REDA + tid * 4;
        g_part[b][tid]      = r[0] + r[1] + r[2] + r[3];
        const float* q = sm + OFF_REDA + 256 + tid * 4;
        g_part[b][64 + tid] = q[0] + q[1] + q[2] + q[3];
    }
}

// ---------------- Kernel B: finalize BN affine + flw column sums (parallel) ----------------
// grid = 74 blocks x 256 threads. Blocks 0..63: channel stats. Blocks 64..73: flw col sums.
__global__ void __launch_bounds__(256) k_finalize(
    const float* __restrict__ g1, const float* __restrict__ be1,
    const float* __restrict__ g2, const float* __restrict__ be2,
    const float* __restrict__ flw)
{
    __shared__ float rs[256], rq[256];
    int j = blockIdx.x, t = threadIdx.x;
    if (j < 64) {
        float s = 0.f, q = 0.f;
        #pragma unroll
        for (int b = t; b < NB_B; b += 256) {
            s += g_part[b][j];
            q += g_part[b][64 + j];
        }
        rs[t] = s; rq[t] = q;
        __syncthreads();
        #pragma unroll
        for (int o = 128; o > 0; o >>= 1) {
            if (t < o) { rs[t] += rs[t + o]; rq[t] += rq[t + o]; }
            __syncthreads();
        }
        if (t == 0) {
            const float inv_n = 1.f / (float)(NB_B * NB_L);
            float mean = rs[0] * inv_n;
            float var  = rq[0] * inv_n - mean * mean;
            float gg = (j < 32) ? __ldg(g1 + j)  : __ldg(g2 + j - 32);
            float bb = (j < 32) ? __ldg(be1 + j) : __ldg(be2 + j - 32);
            float a = gg * rsqrtf(var + 1e-5f);
            g_ab[0][j] = a;
            g_ab[1][j] = bb - mean * a;
        }
    } else {
        int jj = j - 64;                     // jj = half*5 + n
        int n = jj % 5, half = jj / 5;
        const float* p = flw + n * 2048 + half * 1024;
        float s = p[t] + p[t + 256] + p[t + 512] + p[t + 768];
        rs[t] = s;
        __syncthreads();
        #pragma unroll
        for (int o = 128; o > 0; o >>= 1) {
            if (t < o) rs[t] += rs[t + o];
            __syncthreads();
        }
        if (t == 0) g_S[jj] = rs[0];
    }
}

// ---------------- Kernel C: fused BN/ReLU/residual + F + G + output ----------------
__global__ void __launch_bounds__(256) k_pass2(
    const float* __restrict__ src,
    const float* __restrict__ dw1, const float* __restrict__ pw1,
    const float* __restrict__ r1w, const float* __restrict__ r1b,
    const float* __restrict__ dw2, const float* __restrict__ pw2,
    const float* __restrict__ r2w, const float* __restrict__ r2b,
    const float* __restrict__ flw,
    const float* __restrict__ ll1w, const float* __restrict__ ll1b,
    const float* __restrict__ flb, float* __restrict__ out)
{
    extern __shared__ float sm[];
    int b = blockIdx.x, tid = threadIdx.x;

    { // stage flw (L2-resident, 40KB) into shared
        float4*       fdst = reinterpret_cast<float4*>(sm + OFF_FLW);
        const float4* fsrc = reinterpret_cast<const float4*>(flw);
        #pragma unroll
        for (int i = 0; i < 10; i++) fdst[tid + i * 256] = fsrc[tid + i * 256]; // 2560 f4
    }
    stage_src_and_conv(src + (size_t)b * (NB_CIN * NB_L), dw1, dw2, sm, tid);
    __syncthreads();

    int ch = tid & 63, lg = tid >> 6;
    int br = ch >> 5, o = ch & 31;
    const float* pw = (br ? pw2 : pw1) + o * 5;
    const float* rw = (br ? r2w : r1w) + o * 5;
    float rbv = br ? __ldg(r2b + o) : __ldg(r1b + o);
    u64 w[5], rwp[5];
    #pragma unroll
    for (int c = 0; c < 5; c++) {
        float v = __ldg(pw + c); w[c]   = pack2(v, v);
        float u = __ldg(rw + c); rwp[c] = pack2(u, u);
    }
    float av = g_ab[0][ch], bv = g_ab[1][ch];
    u64 a2 = pack2(av, av), bb2 = pack2(bv, bv), rb2 = pack2(rbv, rbv);

    const float* dbase = sm + OFF_D + br * 5 * NB_L;
    const float* sbase = sm + OFF_SRC;
    const float* fbase = sm + OFF_FLW;

    u64 F[10];
    #pragma unroll
    for (int j = 0; j < 10; j++) F[j] = 0;

    for (int k = 0; k < 64; k++) {
        int l0 = (lg + 4 * k) * 4;
        u64 y01 = 0, y23 = 0, r01 = rb2, r23 = rb2;
        #pragma unroll
        for (int c = 0; c < 5; c++) {
            ulonglong2 dv = *reinterpret_cast<const ulonglong2*>(dbase + c * NB_L + l0);
            y01 = fma2(w[c], dv.x, y01);
            y23 = fma2(w[c], dv.y, y23);
            ulonglong2 sv = *reinterpret_cast<const ulonglong2*>(sbase + c * NB_L + l0);
            r01 = fma2(rwp[c], sv.x, r01);
            r23 = fma2(rwp[c], sv.y, r23);
        }
        u64 t01 = fma2(a2, y01, bb2);
        u64 t23 = fma2(a2, y23, bb2);
        float t0, t1, t2, t3, ra0, ra1, ra2, ra3;
        unpack2(t01, t0, t1); unpack2(t23, t2, t3);
        unpack2(r01, ra0, ra1); unpack2(r23, ra2, ra3);
        u64 e01 = pack2(fmaxf(t0, 0.f) * ra0, fmaxf(t1, 0.f) * ra1);
        u64 e23 = pack2(fmaxf(t2, 0.f) * ra2, fmaxf(t3, 0.f) * ra3);
        #pragma unroll
        for (int n = 0; n < 5; n++) {
            ulonglong2 f1 = *reinterpret_cast<const ulonglong2*>(fbase + n * 2048 + l0);
            F[n]     = fma2(e01, f1.x, F[n]);
            F[n]     = fma2(e23, f1.y, F[n]);
            ulonglong2 f2 = *reinterpret_cast<const ulonglong2*>(fbase + n * 2048 + 1024 + l0);
            F[5 + n] = fma2(e01, f2.x, F[5 + n]);
            F[5 + n] = fma2(e23, f2.y, F[5 + n]);
        }
    }
    // per-thread F partials into REDC (disjoint from src/flw regions)
    #pragma unroll
    for (int j = 0; j < 10; j++) {
        float x, y; unpack2(F[j], x, y);
        sm[OFF_REDC + (ch * 4 + lg) * 10 + j] = x + y;
    }
    __syncthreads();   // all REDC partials written; src region now dead -> reuse

    // ---- fused epilogue: G = ll1w.F + ll1b.S, then (i,j) gather-add output ----
    for (int i = tid; i < 832; i += 256) sm[EP_W + i] = __ldg(ll1w + i);
    if (tid < 13) sm[EP_BB + tid] = __ldg(ll1b + tid);
    if (tid < 10) sm[EP_S + tid]  = g_S[tid];
    if (tid < 5)  sm[EP_FB + tid] = __ldg(flb + tid);
    if (tid < 64) {
        #pragma unroll
        for (int j = 0; j < 10; j++) {
            const float* r = sm + OFF_REDC + tid * 40 + j;
            sm[EP_F + tid * 10 + j] = r[0] + r[10] + r[20] + r[30];
        }
    }
    __syncthreads();
    if (tid < 130) {
        int a = tid / 10, j = tid % 10;
        float acc = sm[EP_BB + a] * sm[EP_S + j];
        #pragma unroll 8
        for (int c = 0; c < 64; c++) acc += sm[EP_W + a * 64 + c] * sm[EP_F + c * 10 + j];
        sm[EP_G + tid] = acc;      // sG[a*10+j], j<5: half0 (min), j>=5: half1 (max)
    }
    __syncthreads();
    float* ob = out + (size_t)b * (NB_A * NB_A * NB_NB);
    for (int idx = tid; idx < NB_A * NB_A * NB_NB; idx += 256) {
        int i  = idx / (NB_A * NB_NB);
        int r  = idx % (NB_A * NB_NB);
        int jj = r / NB_NB, n = r % NB_NB;
        int mn = min(i, jj), mx = max(i, jj);
        ob[idx] = sm[EP_G + mn * 10 + n] + sm[EP_G + mx * 10 + 5 + n] + sm[EP_FB + n];
    }
}

// ---------------- launcher ----------------
extern "C" void kernel_launch(void* const* d_in, const int* in_sizes, int n_in,
                              void* d_out, int out_size)
{
    // dw1 is the unique size-25 tensor; everything after it is in fixed order.
    int i0 = -1;
    for (int i = 0; i < n_in; i++) if (in_sizes[i] == 25) { i0 = i; break; }
    if (i0 < 0) i0 = 3; // fallback: src, mask, max_atoms, dw1, ...

    const float* src  = (const float*)d_in[0];
    const float* dw1  = (const float*)d_in[i0 + 0];
    const float* pw1  = (const float*)d_in[i0 + 1];
    const float* g1   = (const float*)d_in[i0 + 2];
    const float* be1  = (const float*)d_in[i0 + 3];
    const float* r1w  = (const float*)d_in[i0 + 4];
    const float* r1b  = (const float*)d_in[i0 + 5];
    const float* dw2  = (const float*)d_in[i0 + 6];
    const float* pw2  = (const float*)d_in[i0 + 7];
    const float* g2   = (const float*)d_in[i0 + 8];
    const float* be2  = (const float*)d_in[i0 + 9];
    const float* r2w  = (const float*)d_in[i0 + 10];
    const float* r2b  = (const float*)d_in[i0 + 11];
    const float* ll1w = (const float*)d_in[i0 + 12];
    const float* ll1b = (const float*)d_in[i0 + 13];
    const float* flw  = (const float*)d_in[i0 + 14];
    const float* flb  = (const float*)d_in[i0 + 15];
    float* out = (float*)d_out;
    (void)out_size; (void)n_in;

    const int shA = SMEM_A_FLOATS * (int)sizeof(float);   // 63488 B
    const int shC = SMEM_C_FLOATS * (int)sizeof(float);   // 112640 B
    cudaFuncSetAttribute(k_stats, cudaFuncAttributeMaxDynamicSharedMemorySize, shA);
    cudaFuncSetAttribute(k_pass2, cudaFuncAttributeMaxDynamicSharedMemorySize, shC);

    k_stats<<<NB_B, 256, shA>>>(src, dw1, pw1, dw2, pw2);
    k_finalize<<<74, 256>>>(g1, be1, g2, be2, flw);
    k_pass2<<<NB_B, 256, shC>>>(src, dw1, pw1, r1w, r1b, dw2, pw2, r2w, r2b, flw,
                                ll1w, ll1b, flb, out);
}

// round 6
// speedup vs baseline: 2.1067x; 1.1133x over previous
#include <cuda_runtime.h>

// Problem constants (fixed by the reference)
#define NB_B   512
#define NB_CIN 5
#define NB_L   1024
#define NB_NCH 64     // 2*COUT
#define NB_A   13
#define NB_NB  5

#define PADL   1032   // padded src row: 4 zero + 1024 + 4 zero

typedef unsigned long long u64;

// ---------------- scratch (static device globals; no allocation) ----------------
__device__ float g_gram[NB_B][40];   // per-b: s1[5], s2[5], G1[15], G2[15]
__device__ float g_ab[2][NB_NCH];    // BN affine: scale a, shift beta
__device__ float g_S[10];            // column sums of flw halves

// ---------------- packed f32x2 helpers (Blackwell) ----------------
__device__ __forceinline__ u64 fma2(u64 a, u64 b, u64 c) {
    u64 d; asm("fma.rn.f32x2 %0, %1, %2, %3;" : "=l"(d) : "l"(a), "l"(b), "l"(c)); return d;
}
__device__ __forceinline__ u64 pack2(float x, float y) {
    u64 r; asm("mov.b64 %0, {%1, %2};" : "=l"(r) : "f"(x), "f"(y)); return r;
}
__device__ __forceinline__ void unpack2(u64 v, float& x, float& y) {
    asm("mov.b64 {%0, %1}, %2;" : "=f"(x), "=f"(y) : "l"(v));
}

// ---------------- shared layouts (floats) ----------------
// kernel A: [src 5*1032][red 256*41][red2 240]
#define OFF_REDK  (5 * PADL)                    // 5160
#define OFF_RED2  (OFF_REDK + 256 * 41)         // 15656
#define SMEM_A_FLOATS (OFF_RED2 + 240)          // 15896 -> 63584 B
// kernel C: [src 5*1032][d 10*1024][flw 10*1024][redc 2560]
#define OFF_D     (5 * PADL)                    // 5160
#define OFF_FLW   (OFF_D + 10 * NB_L)           // 15400
#define OFF_REDC  (OFF_FLW + 10 * NB_L)         // 25640
#define SMEM_C_FLOATS (OFF_REDC + 64 * 4 * 10)  // 28200 -> 112800 B

// Epilogue aliases into the (dead-after-mainloop) src region of kernel C smem
#define EP_W   0                  // 832  : ll1w
#define EP_F   (EP_W + 832)       // 640  : reduced F[ch][j]
#define EP_G   (EP_F + 640)       // 130
#define EP_BB  (EP_G + 130)       // 13   : ll1b
#define EP_S   (EP_BB + 13)       // 10   : g_S
#define EP_FB  (EP_S + 10)        // 5    : flb

// Stage one batch row of src into zero-padded shared rows. Caller syncs after.
__device__ __forceinline__ void stage_src_padded(
    const float* __restrict__ src_b, float* sm, int tid)
{
    if (tid < 40) {                    // zero the 8 halo floats per channel
        int c = tid >> 3, p = tid & 7;
        sm[c * PADL + (p < 4 ? p : 1024 + p)] = 0.f;
    }
    const float4* ssrc = reinterpret_cast<const float4*>(src_b);
    #pragma unroll
    for (int i = 0; i < 5; i++) {
        int g = tid + i * 256;         // quad index in [0,1280)
        int c = g >> 8, q = g & 255;
        float4 v = ssrc[g];
        *reinterpret_cast<float4*>(sm + c * PADL + 4 + q * 4) = v;
    }
}

// Compute both depthwise convs for 4 consecutive l (l0..l0+3), register-resident.
__device__ __forceinline__ void conv4(
    const float* sm, int l0, const float* w1, const float* w2,
    float d1[5][4], float d2[5][4])
{
    #pragma unroll
    for (int c = 0; c < 5; c++) {
        const float* base = sm + c * PADL + 4 + l0;
        float4 A  = *reinterpret_cast<const float4*>(base - 4);
        float4 Bv = *reinterpret_cast<const float4*>(base);
        float4 Cv = *reinterpret_cast<const float4*>(base + 4);
        float xa[8] = {A.z, A.w, Bv.x, Bv.y, Bv.z, Bv.w, Cv.x, Cv.y};
        #pragma unroll
        for (int l = 0; l < 4; l++) {
            d1[c][l] = w1[c*5+0]*xa[l]   + w1[c*5+1]*xa[l+1] + w1[c*5+2]*xa[l+2]
                     + w1[c*5+3]*xa[l+3] + w1[c*5+4]*xa[l+4];
            d2[c][l] = w2[c*3+0]*xa[l+1] + w2[c*3+1]*xa[l+2] + w2[c*3+2]*xa[l+3];
        }
    }
}

// ---------------- Kernel A: per-b Gram statistics of d (register-resident) ----------------
__global__ void __launch_bounds__(256) k_stats(
    const float* __restrict__ src,
    const float* __restrict__ dw1, const float* __restrict__ dw2)
{
    extern __shared__ float sm[];
    int b = blockIdx.x, tid = threadIdx.x;
    stage_src_padded(src + (size_t)b * (NB_CIN * NB_L), sm, tid);

    float w1[25], w2[15];
    #pragma unroll
    for (int i = 0; i < 25; i++) w1[i] = __ldg(dw1 + i);
    #pragma unroll
    for (int i = 0; i < 15; i++) w2[i] = __ldg(dw2 + i);
    __syncthreads();

    float d1[5][4], d2[5][4];
    conv4(sm, tid * 4, w1, w2, d1, d2);

    float s1a[5], s2a[5], g1a[15], g2a[15];
    #pragma unroll
    for (int c = 0; c < 5; c++) { s1a[c] = 0.f; s2a[c] = 0.f; }
    #pragma unroll
    for (int i = 0; i < 15; i++) { g1a[i] = 0.f; g2a[i] = 0.f; }

    #pragma unroll
    for (int l = 0; l < 4; l++) {
        #pragma unroll
        for (int c = 0; c < 5; c++) { s1a[c] += d1[c][l]; s2a[c] += d2[c][l]; }
        int idx = 0;
        #pragma unroll
        for (int c = 0; c < 5; c++)
            #pragma unroll
            for (int c2 = 0; c2 <= c; c2++) {
                g1a[idx] += d1[c][l] * d1[c2][l];
                g2a[idx] += d2[c][l] * d2[c2][l];
                idx++;
            }
    }

    // block reduction of 40 accumulators (stride-41 layout: conflict-free)
    float* rr = sm + OFF_REDK + tid * 41;
    #pragma unroll
    for (int c = 0; c < 5; c++) { rr[c] = s1a[c]; rr[5 + c] = s2a[c]; }
    #pragma unroll
    for (int i = 0; i < 15; i++) { rr[10 + i] = g1a[i]; rr[25 + i] = g2a[i]; }
    __syncthreads();
    if (tid < 240) {
        int j = tid % 40, ck = tid / 40;       // 6 chunks per accumulator
        float s = 0.f;
        for (int c = ck; c < 256; c += 6) s += sm[OFF_REDK + c * 41 + j];
        sm[OFF_RED2 + ck * 40 + j] = s;
    }
    __syncthreads();
    if (tid < 40) {
        float s = 0.f;
        #pragma unroll
        for (int ck = 0; ck < 6; ck++) s += sm[OFF_RED2 + ck * 40 + tid];
        g_gram[b][tid] = s;
    }
}

// ---------------- Kernel B: finalize BN affine (from Gram) + flw column sums ----------------
// grid = 11 blocks x 256. Block 0: Gram reduce + affine. Blocks 1..10: flw col sums.
__global__ void __launch_bounds__(256) k_finalize(
    const float* __restrict__ g1, const float* __restrict__ be1,
    const float* __restrict__ g2, const float* __restrict__ be2,
    const float* __restrict__ pw1, const float* __restrict__ pw2,
    const float* __restrict__ flw)
{
    __shared__ float sp[240], sM[40], rs[256];
    int blk = blockIdx.x, t = threadIdx.x;
    if (blk == 0) {
        if (t < 240) {
            int j = t % 40, ck = t / 40;
            float s = 0.f;
            for (int b = ck; b < NB_B; b += 6) s += g_gram[b][j];
            sp[t] = s;
        }
        __syncthreads();
        if (t < 40) {
            float s = 0.f;
            #pragma unroll
            for (int ck = 0; ck < 6; ck++) s += sp[ck * 40 + t];
            sM[t] = s;
        }
        __syncthreads();
        if (t < 64) {
            int br = t >> 5, o = t & 31;
            const float* pwp = (br ? pw2 : pw1) + o * 5;
            float pw[5];
            #pragma unroll
            for (int c = 0; c < 5; c++) pw[c] = __ldg(pwp + c);
            const float* Ss = sM + br * 5;
            const float* Ms = sM + 10 + br * 15;
            float mn = 0.f, ss = 0.f;
            #pragma unroll
            for (int c = 0; c < 5; c++) mn += pw[c] * Ss[c];
            int idx = 0;
            #pragma unroll
            for (int c = 0; c < 5; c++)
                #pragma unroll
                for (int c2 = 0; c2 <= c; c2++) {
                    float coef = (c == c2) ? pw[c] * pw[c] : 2.f * pw[c] * pw[c2];
                    ss += coef * Ms[idx++];
                }
            const float inv_n = 1.f / (float)(NB_B * NB_L);
            float mean = mn * inv_n;
            float var  = ss * inv_n - mean * mean;
            float gg = (t < 32) ? __ldg(g1 + t)  : __ldg(g2 + t - 32);
            float bb = (t < 32) ? __ldg(be1 + t) : __ldg(be2 + t - 32);
            float a = gg * rsqrtf(var + 1e-5f);
            g_ab[0][t] = a;
            g_ab[1][t] = bb - mean * a;
        }
    } else {
        int jj = blk - 1;                    // jj = half*5 + n
        int n = jj % 5, half = jj / 5;
        const float* p = flw + n * 2048 + half * 1024;
        rs[t] = p[t] + p[t + 256] + p[t + 512] + p[t + 768];
        __syncthreads();
        #pragma unroll
        for (int o = 128; o > 0; o >>= 1) {
            if (t < o) rs[t] += rs[t + o];
            __syncthreads();
        }
        if (t == 0) g_S[jj] = rs[0];
    }
}

// ---------------- Kernel C: fused BN/ReLU/residual + F + G + output ----------------
__global__ void __launch_bounds__(256) k_pass2(
    const float* __restrict__ src,
    const float* __restrict__ dw1, const float* __restrict__ pw1,
    const float* __restrict__ r1w, const float* __restrict__ r1b,
    const float* __restrict__ dw2, const float* __restrict__ pw2,
    const float* __restrict__ r2w, const float* __restrict__ r2b,
    const float* __restrict__ flw,
    const float* __restrict__ ll1w, const float* __restrict__ ll1b,
    const float* __restrict__ flb, float* __restrict__ out)
{
    extern __shared__ float sm[];
    int b = blockIdx.x, tid = threadIdx.x;

    { // stage flw (L2-resident, 40KB) into shared
        float4*       fdst = reinterpret_cast<float4*>(sm + OFF_FLW);
        const float4* fsrc = reinterpret_cast<const float4*>(flw);
        #pragma unroll
        for (int i = 0; i < 10; i++) fdst[tid + i * 256] = fsrc[tid + i * 256]; // 2560 f4
    }
    stage_src_padded(src + (size_t)b * (NB_CIN * NB_L), sm, tid);

    float w1[25], w2[15];
    #pragma unroll
    for (int i = 0; i < 25; i++) w1[i] = __ldg(dw1 + i);
    #pragma unroll
    for (int i = 0; i < 15; i++) w2[i] = __ldg(dw2 + i);
    __syncthreads();

    { // depthwise convs -> shared d region (float4 stores)
        int l0 = tid * 4;
        float d1[5][4], d2[5][4];
        conv4(sm, l0, w1, w2, d1, d2);
        #pragma unroll
        for (int c = 0; c < 5; c++) {
            *reinterpret_cast<float4*>(sm + OFF_D + c * NB_L + l0) =
                make_float4(d1[c][0], d1[c][1], d1[c][2], d1[c][3]);
            *reinterpret_cast<float4*>(sm + OFF_D + (5 + c) * NB_L + l0) =
                make_float4(d2[c][0], d2[c][1], d2[c][2], d2[c][3]);
        }
    }
    __syncthreads();

    int ch = tid & 63, lg = tid >> 6;       // warp lanes share lg -> LDS broadcasts
    int br = ch >> 5, o = ch & 31;
    const float* pw = (br ? pw2 : pw1) + o * 5;
    const float* rw = (br ? r2w : r1w) + o * 5;
    float rbv = br ? __ldg(r2b + o) : __ldg(r1b + o);
    u64 w[5], rwp[5];
    #pragma unroll
    for (int c = 0; c < 5; c++) {
        float v = __ldg(pw + c); w[c]   = pack2(v, v);
        float u = __ldg(rw + c); rwp[c] = pack2(u, u);
    }
    float av = g_ab[0][ch], bv = g_ab[1][ch];
    u64 a2 = pack2(av, av), bb2 = pack2(bv, bv), rb2 = pack2(rbv, rbv);

    const float* dbase = sm + OFF_D + br * 5 * NB_L;
    const float* fbase = sm + OFF_FLW;

    u64 F[10];
    #pragma unroll
    for (int j = 0; j < 10; j++) F[j] = 0;

    for (int k = 0; k < 64; k++) {
        int l0 = (lg + 4 * k) * 4;
        u64 y01 = 0, y23 = 0, r01 = rb2, r23 = rb2;
        #pragma unroll
        for (int c = 0; c < 5; c++) {
            ulonglong2 dv = *reinterpret_cast<const ulonglong2*>(dbase + c * NB_L + l0);
            y01 = fma2(w[c], dv.x, y01);
            y23 = fma2(w[c], dv.y, y23);
            ulonglong2 sv = *reinterpret_cast<const ulonglong2*>(sm + c * PADL + 4 + l0);
            r01 = fma2(rwp[c], sv.x, r01);
            r23 = fma2(rwp[c], sv.y, r23);
        }
        u64 t01 = fma2(a2, y01, bb2);
        u64 t23 = fma2(a2, y23, bb2);
        float t0, t1, t2, t3, ra0, ra1, ra2, ra3;
        unpack2(t01, t0, t1); unpack2(t23, t2, t3);
        unpack2(r01, ra0, ra1); unpack2(r23, ra2, ra3);
        u64 e01 = pack2(fmaxf(t0, 0.f) * ra0, fmaxf(t1, 0.f) * ra1);
        u64 e23 = pack2(fmaxf(t2, 0.f) * ra2, fmaxf(t3, 0.f) * ra3);
        #pragma unroll
        for (int n = 0; n < 5; n++) {
            ulonglong2 f1 = *reinterpret_cast<const ulonglong2*>(fbase + n * 2048 + l0);
            F[n]     = fma2(e01, f1.x, F[n]);
            F[n]     = fma2(e23, f1.y, F[n]);
            ulonglong2 f2 = *reinterpret_cast<const ulonglong2*>(fbase + n * 2048 + 1024 + l0);
            F[5 + n] = fma2(e01, f2.x, F[5 + n]);
            F[5 + n] = fma2(e23, f2.y, F[5 + n]);
        }
    }
    // per-thread F partials into REDC (disjoint from src/flw regions)
    #pragma unroll
    for (int j = 0; j < 10; j++) {
        float x, y; unpack2(F[j], x, y);
        sm[OFF_REDC + (ch * 4 + lg) * 10 + j] = x + y;
    }
    __syncthreads();   // all REDC partials written; src region now dead -> reuse

    // ---- fused epilogue: G = ll1w.F + ll1b.S, then (i,j) gather-add output ----
    for (int i = tid; i < 832; i += 256) sm[EP_W + i] = __ldg(ll1w + i);
    if (tid < 13) sm[EP_BB + tid] = __ldg(ll1b + tid);
    if (tid < 10) sm[EP_S + tid]  = g_S[tid];
    if (tid < 5)  sm[EP_FB + tid] = __ldg(flb + tid);
    if (tid < 64) {
        #pragma unroll
        for (int j = 0; j < 10; j++) {
            const float* r = sm + OFF_REDC + tid * 40 + j;
            sm[EP_F + tid * 10 + j] = r[0] + r[10] + r[20] + r[30];
        }
    }
    __syncthreads();
    if (tid < 130) {
        int a = tid / 10, j = tid % 10;
        float acc = sm[EP_BB + a] * sm[EP_S + j];
        #pragma unroll 8
        for (int c = 0; c < 64; c++) acc += sm[EP_W + a * 64 + c] * sm[EP_F + c * 10 + j];
        sm[EP_G + tid] = acc;      // sG[a*10+j], j<5: half0 (min), j>=5: half1 (max)
    }
    __syncthreads();
    float* ob = out + (size_t)b * (NB_A * NB_A * NB_NB);
    for (int idx = tid; idx < NB_A * NB_A * NB_NB; idx += 256) {
        int i  = idx / (NB_A * NB_NB);
        int r  = idx % (NB_A * NB_NB);
        int jj = r / NB_NB, n = r % NB_NB;
        int mn = min(i, jj), mx = max(i, jj);
        ob[idx] = sm[EP_G + mn * 10 + n] + sm[EP_G + mx * 10 + 5 + n] + sm[EP_FB + n];
    }
}

// ---------------- launcher ----------------
extern "C" void kernel_launch(void* const* d_in, const int* in_sizes, int n_in,
                              void* d_out, int out_size)
{
    // dw1 is the unique size-25 tensor; everything after it is in fixed order.
    int i0 = -1;
    for (int i = 0; i < n_in; i++) if (in_sizes[i] == 25) { i0 = i; break; }
    if (i0 < 0) i0 = 3; // fallback: src, mask, max_atoms, dw1, ...

    const float* src  = (const float*)d_in[0];
    const float* dw1  = (const float*)d_in[i0 + 0];
    const float* pw1  = (const float*)d_in[i0 + 1];
    const float* g1   = (const float*)d_in[i0 + 2];
    const float* be1  = (const float*)d_in[i0 + 3];
    const float* r1w  = (const float*)d_in[i0 + 4];
    const float* r1b  = (const float*)d_in[i0 + 5];
    const float* dw2  = (const float*)d_in[i0 + 6];
    const float* pw2  = (const float*)d_in[i0 + 7];
    const float* g2   = (const float*)d_in[i0 + 8];
    const float* be2  = (const float*)d_in[i0 + 9];
    const float* r2w  = (const float*)d_in[i0 + 10];
    const float* r2b  = (const float*)d_in[i0 + 11];
    const float* ll1w = (const float*)d_in[i0 + 12];
    const float* ll1b = (const float*)d_in[i0 + 13];
    const float* flw  = (const float*)d_in[i0 + 14];
    const float* flb  = (const float*)d_in[i0 + 15];
    float* out = (float*)d_out;
    (void)out_size; (void)n_in;

    const int shA = SMEM_A_FLOATS * (int)sizeof(float);   // 63584 B
    const int shC = SMEM_C_FLOATS * (int)sizeof(float);   // 112800 B
    cudaFuncSetAttribute(k_stats, cudaFuncAttributeMaxDynamicSharedMemorySize, shA);
    cudaFuncSetAttribute(k_pass2, cudaFuncAttributeMaxDynamicSharedMemorySize, shC);

    k_stats<<<NB_B, 256, shA>>>(src, dw1, dw2);
    k_finalize<<<11, 256>>>(g1, be1, g2, be2, pw1, pw2, flw);
    k_pass2<<<NB_B, 256, shC>>>(src, dw1, pw1, r1w, r1b, dw2, pw2, r2w, r2b, flw,
                                ll1w, ll1b, flb, out);
}